// round 14
// baseline (speedup 1.0000x reference)
#include <cuda_runtime.h>
#include <cstdint>

// out[i,j] = | prod_k cos((x[i,k]-y[j,k])/2) |
//
// Per wire: cos((a-b)/2) = cos(a/2)cos(b/2) + sin(a/2)sin(b/2)
// Pair wires (2k,2k+1): t_2k*t_2k+1 = X.Y (4-dim dot),
//   X = (c0c1, c0s1, s0c1, s0s1), same for Y.
//
// Two kernels:
//  A) trig_kernel: per (row, pair) compute the 4 components ONCE into
//     L2-resident __device__ tables (x: duplicated-pair float4 for packed
//     f32x2 operands; y: SoA floats).
//  B) qk_kernel: fill = pure coalesced copies (no MUFU, no packing), then
//     the plateau-tested packed-f32x2 main loop (64x64 tile, occ 6).

#define D       16
#define KP      8
#define BM      64
#define BN      64
#define NT      128
#define MAXROWS 2048

__device__ float4 g_xtab[KP][2][MAXROWS];   // {w0,w0,w1,w1} / {w2,w2,w3,w3}
__device__ float  g_ytab[KP][4][MAXROWS];   // SoA per component

#define FMA_X2(d, a, b, c) \
    asm("fma.rn.f32x2 %0, %1, %2, %3;" : "=l"(d) : "l"(a), "l"(b), "l"(c))
#define MUL_X2(d, a, b) \
    asm("mul.rn.f32x2 %0, %1, %2;" : "=l"(d) : "l"(a), "l"(b))

// ---------------- Kernel A: trig tables ----------------
__global__ __launch_bounds__(256)
void trig_kernel(const float* __restrict__ x, const float* __restrict__ y,
                 int n, int m) {
    const int t  = blockIdx.x * blockDim.x + threadIdx.x;
    const int nx = n * KP;
    if (t < nx) {
        const int kp = t / n;          // consecutive t -> consecutive rows
        const int r  = t - kp * n;
        float2 v = *reinterpret_cast<const float2*>(x + (size_t)r * D + 2 * kp);
        float s0, c0, s1, c1;
        __sincosf(0.5f * v.x, &s0, &c0);
        __sincosf(0.5f * v.y, &s1, &c1);
        float w0 = c0*c1, w1 = c0*s1, w2 = s0*c1, w3 = s0*s1;
        g_xtab[kp][0][r] = make_float4(w0, w0, w1, w1);
        g_xtab[kp][1][r] = make_float4(w2, w2, w3, w3);
    } else {
        const int u  = t - nx;
        if (u >= m * KP) return;
        const int kp = u / m;
        const int r  = u - kp * m;
        float2 v = *reinterpret_cast<const float2*>(y + (size_t)r * D + 2 * kp);
        float s0, c0, s1, c1;
        __sincosf(0.5f * v.x, &s0, &c0);
        __sincosf(0.5f * v.y, &s1, &c1);
        g_ytab[kp][0][r] = c0*c1;
        g_ytab[kp][1][r] = c0*s1;
        g_ytab[kp][2][r] = s0*c1;
        g_ytab[kp][3][r] = s0*s1;
    }
}

// ---------------- Kernel B: main GEMM-like loop ----------------
__global__ __launch_bounds__(NT, 6)
void qk_kernel(float* __restrict__ out, int n, int m) {
    __shared__ float4 sxd[KP][2][BM];   // 8 KB
    __shared__ float  syp[KP][4][BN];   // 8 KB

    const int tid = threadIdx.x;
    const int bi  = blockIdx.y * BM;
    const int bj  = blockIdx.x * BN;

    // ---- Fill: pure coalesced copies from L2-resident tables ----
    // x side: KP*2*BM float4 = 1024 float4
#pragma unroll
    for (int it = 0; it < (KP * 2 * BM) / NT; it++) {
        const int idx = it * NT + tid;
        const int kp  = idx >> 7;            // /(2*BM)
        const int h   = (idx >> 6) & 1;
        const int rr  = idx & 63;
        sxd[kp][h][rr] = g_xtab[kp][h][bi + rr];
    }
    // y side: KP*4*BN floats = 2048 floats = 512 float4 (bj % 64 == 0)
#pragma unroll
    for (int it = 0; it < (KP * 4 * (BN / 4)) / NT; it++) {
        const int idx = it * NT + tid;
        const int kp  = idx >> 6;            // /(4*16)
        const int c   = (idx >> 4) & 3;
        const int q   = idx & 15;
        *reinterpret_cast<float4*>(&syp[kp][c][4 * q]) =
            *reinterpret_cast<const float4*>(&g_ytab[kp][c][bj + 4 * q]);
    }
    __syncthreads();

    // ---- Main: 8 rows x 4 contiguous cols per thread ----
    // i = bi + ty + 8*ii (ii = 0..7);  j = bj + 4*tx + {0..3}
    const int tx = tid & 15;
    const int ty = tid >> 4;

    uint64_t acc[8][2];

    // y operand double buffer
    uint64_t yb[4][2], ybn[4][2];
#pragma unroll
    for (int c = 0; c < 4; c++) {
        float4 q = *reinterpret_cast<const float4*>(&syp[0][c][4 * tx]);
        yb[c][0] = *reinterpret_cast<const uint64_t*>(&q.x);
        yb[c][1] = *reinterpret_cast<const uint64_t*>(&q.z);
    }

#pragma unroll
    for (int kp = 0; kp < KP; kp++) {
        if (kp + 1 < KP) {
#pragma unroll
            for (int c = 0; c < 4; c++) {
                float4 q = *reinterpret_cast<const float4*>(&syp[kp + 1][c][4 * tx]);
                ybn[c][0] = *reinterpret_cast<const uint64_t*>(&q.x);
                ybn[c][1] = *reinterpret_cast<const uint64_t*>(&q.z);
            }
        }

#pragma unroll
        for (int ii = 0; ii < 8; ii++) {
            const int row = ty + 8 * ii;
            float4 p0 = sxd[kp][0][row];   // {w0,w0,w1,w1}
            float4 p1 = sxd[kp][1][row];   // {w2,w2,w3,w3}
            uint64_t x0 = *reinterpret_cast<const uint64_t*>(&p0.x);
            uint64_t x1 = *reinterpret_cast<const uint64_t*>(&p0.z);
            uint64_t x2 = *reinterpret_cast<const uint64_t*>(&p1.x);
            uint64_t x3 = *reinterpret_cast<const uint64_t*>(&p1.z);
#pragma unroll
            for (int jj2 = 0; jj2 < 2; jj2++) {
                uint64_t t;
                MUL_X2(t, x0, yb[0][jj2]);
                FMA_X2(t, x1, yb[1][jj2], t);
                FMA_X2(t, x2, yb[2][jj2], t);
                FMA_X2(t, x3, yb[3][jj2], t);
                if (kp == 0) acc[ii][jj2] = t;
                else         MUL_X2(acc[ii][jj2], acc[ii][jj2], t);
            }
        }

        if (kp + 1 < KP) {
#pragma unroll
            for (int c = 0; c < 4; c++) {
                yb[c][0] = ybn[c][0];
                yb[c][1] = ybn[c][1];
            }
        }
    }

    // ---- Store: packed abs + one STG.128 per row ----
    const uint64_t ABS2 = 0x7FFFFFFF7FFFFFFFULL;
    if (bi + BM <= n && bj + BN <= m) {
#pragma unroll
        for (int ii = 0; ii < 8; ii++) {
            uint64_t a0 = acc[ii][0] & ABS2;
            uint64_t a1 = acc[ii][1] & ABS2;
            float4 v;
            v.x = __uint_as_float((uint32_t)a0);
            v.y = __uint_as_float((uint32_t)(a0 >> 32));
            v.z = __uint_as_float((uint32_t)a1);
            v.w = __uint_as_float((uint32_t)(a1 >> 32));
            *reinterpret_cast<float4*>(
                out + (size_t)(bi + ty + 8 * ii) * m + (bj + 4 * tx)) = v;
        }
    } else {
#pragma unroll
        for (int ii = 0; ii < 8; ii++) {
            int gi = bi + ty + 8 * ii;
            if (gi >= n) continue;
#pragma unroll
            for (int jj2 = 0; jj2 < 2; jj2++) {
                uint64_t a = acc[ii][jj2] & ABS2;
                int gj = bj + 4 * tx + 2 * jj2;
                if (gj     < m) out[(size_t)gi * m + gj]     = __uint_as_float((uint32_t)a);
                if (gj + 1 < m) out[(size_t)gi * m + gj + 1] = __uint_as_float((uint32_t)(a >> 32));
            }
        }
    }
}

extern "C" void kernel_launch(void* const* d_in, const int* in_sizes, int n_in,
                              void* d_out, int out_size) {
    const float* x = (const float*)d_in[0];
    const float* y = (const float*)d_in[1];
    float* out = (float*)d_out;
    int n = in_sizes[0] / D;
    int m = in_sizes[1] / D;
    if (n > MAXROWS) n = MAXROWS;
    if (m > MAXROWS) m = MAXROWS;

    const int total = (n + m) * KP;
    trig_kernel<<<(total + 255) / 256, 256>>>(x, y, n, m);

    dim3 grid((m + BN - 1) / BN, (n + BM - 1) / BM);
    qk_kernel<<<grid, NT>>>(out, n, m);
}

// round 15
// speedup vs baseline: 1.2844x; 1.2844x over previous
#include <cuda_runtime.h>
#include <cstdint>

// out[i,j] = | prod_k cos((x[i,k]-y[j,k])/2) |
//
// Per wire: cos((a-b)/2) = cos(a/2)cos(b/2) + sin(a/2)sin(b/2)
// Pair wires (2k,2k+1): t_2k*t_2k+1 = X.Y (4-dim dot),
//   X = (c0c1, c0s1, s0c1, s0s1), same for Y.
//
// Single kernel. Main loop flattened to 64 fully-unrolled (kp,ii) steps with
// an explicit depth-1 double buffer on the x operands so every LDS.128
// latency is overlapped by the previous step's 10 packed FMAs.

#define D    16
#define KP   8
#define BM   64
#define BN   64
#define NT   128

#define FMA_X2(d, a, b, c) \
    asm("fma.rn.f32x2 %0, %1, %2, %3;" : "=l"(d) : "l"(a), "l"(b), "l"(c))
#define MUL_X2(d, a, b) \
    asm("mul.rn.f32x2 %0, %1, %2;" : "=l"(d) : "l"(a), "l"(b))

__global__ __launch_bounds__(NT, 6)
void qk_kernel(const float* __restrict__ x, const float* __restrict__ y,
               float* __restrict__ out, int n, int m) {
    __shared__ float4 sxd[KP][2][BM];   // 8 KB: {w0,w0,w1,w1},{w2,w2,w3,w3}
    __shared__ float  syp[KP][4][BN];   // 8 KB: SoA per component

    const int tid = threadIdx.x;
    const int bi  = blockIdx.y * BM;
    const int bj  = blockIdx.x * BN;

    // ---- Fill: threads 0..63 -> x rows, 64..127 -> y rows ----
    {
        const bool isY  = (tid >= BM);
        const int  r    = isY ? (tid - BM) : tid;
        const int  gr   = (isY ? bj : bi) + r;
        const int  lim  = isY ? m : n;
        const float* src = isY ? y : x;

        float v[D];
        if (gr < lim) {
            const float4* p = reinterpret_cast<const float4*>(src + (size_t)gr * D);
            float4 a = p[0], b = p[1], c = p[2], d = p[3];
            v[0]=a.x;  v[1]=a.y;  v[2]=a.z;  v[3]=a.w;
            v[4]=b.x;  v[5]=b.y;  v[6]=b.z;  v[7]=b.w;
            v[8]=c.x;  v[9]=c.y;  v[10]=c.z; v[11]=c.w;
            v[12]=d.x; v[13]=d.y; v[14]=d.z; v[15]=d.w;
        } else {
#pragma unroll
            for (int k = 0; k < D; k++) v[k] = 0.0f;  // cos(0)=1 padding
        }

#pragma unroll
        for (int kp = 0; kp < KP; kp++) {
            float s0, c0, s1, c1;
            __sincosf(0.5f * v[2*kp + 0], &s0, &c0);
            __sincosf(0.5f * v[2*kp + 1], &s1, &c1);
            float w0 = c0*c1, w1 = c0*s1, w2 = s0*c1, w3 = s0*s1;
            if (isY) {
                syp[kp][0][r] = w0; syp[kp][1][r] = w1;
                syp[kp][2][r] = w2; syp[kp][3][r] = w3;
            } else {
                sxd[kp][0][r] = make_float4(w0, w0, w1, w1);
                sxd[kp][1][r] = make_float4(w2, w2, w3, w3);
            }
        }
    }
    __syncthreads();

    // ---- Main: 8 rows x 4 contiguous cols per thread ----
    // i = bi + ty + 8*ii (ii = 0..7);  j = bj + 4*tx + {0..3}
    const int tx = tid & 15;
    const int ty = tid >> 4;

    uint64_t acc[8][2];
    uint64_t yb[4][2];      // y operands for current kp
    float4   xb[2][2];      // x operand double buffer

    // preload step 0
    xb[0][0] = sxd[0][0][ty];
    xb[0][1] = sxd[0][1][ty];

#pragma unroll
    for (int step = 0; step < KP * 8; step++) {
        const int kp  = step >> 3;
        const int ii  = step & 7;
        const int cur = step & 1;
        const int nxt = cur ^ 1;

        // y operands: load once per kp, at its first step
        if (ii == 0) {
#pragma unroll
            for (int c = 0; c < 4; c++) {
                float4 q = *reinterpret_cast<const float4*>(&syp[kp][c][4 * tx]);
                yb[c][0] = *reinterpret_cast<const uint64_t*>(&q.x);
                yb[c][1] = *reinterpret_cast<const uint64_t*>(&q.z);
            }
        }

        // x prefetch for next step (covers the LDS latency with this
        // step's FMA stream)
        if (step + 1 < KP * 8) {
            const int ns  = step + 1;
            const int nkp = ns >> 3;
            const int nii = ns & 7;
            xb[nxt][0] = sxd[nkp][0][ty + 8 * nii];
            xb[nxt][1] = sxd[nkp][1][ty + 8 * nii];
        }

        const float4 p0 = xb[cur][0];   // {w0,w0,w1,w1}
        const float4 p1 = xb[cur][1];   // {w2,w2,w3,w3}
        const uint64_t x0 = *reinterpret_cast<const uint64_t*>(&p0.x);
        const uint64_t x1 = *reinterpret_cast<const uint64_t*>(&p0.z);
        const uint64_t x2 = *reinterpret_cast<const uint64_t*>(&p1.x);
        const uint64_t x3 = *reinterpret_cast<const uint64_t*>(&p1.z);
#pragma unroll
        for (int jj2 = 0; jj2 < 2; jj2++) {
            uint64_t t;
            MUL_X2(t, x0, yb[0][jj2]);
            FMA_X2(t, x1, yb[1][jj2], t);
            FMA_X2(t, x2, yb[2][jj2], t);
            FMA_X2(t, x3, yb[3][jj2], t);
            if (kp == 0) acc[ii][jj2] = t;
            else         MUL_X2(acc[ii][jj2], acc[ii][jj2], t);
        }
    }

    // ---- Store: packed abs + one STG.128 per row ----
    const uint64_t ABS2 = 0x7FFFFFFF7FFFFFFFULL;
    if (bi + BM <= n && bj + BN <= m) {
#pragma unroll
        for (int ii = 0; ii < 8; ii++) {
            uint64_t a0 = acc[ii][0] & ABS2;
            uint64_t a1 = acc[ii][1] & ABS2;
            float4 v;
            v.x = __uint_as_float((uint32_t)a0);
            v.y = __uint_as_float((uint32_t)(a0 >> 32));
            v.z = __uint_as_float((uint32_t)a1);
            v.w = __uint_as_float((uint32_t)(a1 >> 32));
            *reinterpret_cast<float4*>(
                out + (size_t)(bi + ty + 8 * ii) * m + (bj + 4 * tx)) = v;
        }
    } else {
#pragma unroll
        for (int ii = 0; ii < 8; ii++) {
            int gi = bi + ty + 8 * ii;
            if (gi >= n) continue;
#pragma unroll
            for (int jj2 = 0; jj2 < 2; jj2++) {
                uint64_t a = acc[ii][jj2] & ABS2;
                int gj = bj + 4 * tx + 2 * jj2;
                if (gj     < m) out[(size_t)gi * m + gj]     = __uint_as_float((uint32_t)a);
                if (gj + 1 < m) out[(size_t)gi * m + gj + 1] = __uint_as_float((uint32_t)(a >> 32));
            }
        }
    }
}

extern "C" void kernel_launch(void* const* d_in, const int* in_sizes, int n_in,
                              void* d_out, int out_size) {
    const float* x = (const float*)d_in[0];
    const float* y = (const float*)d_in[1];
    float* out = (float*)d_out;
    int n = in_sizes[0] / D;
    int m = in_sizes[1] / D;

    dim3 block(NT);
    dim3 grid((m + BN - 1) / BN, (n + BM - 1) / BM);
    qk_kernel<<<grid, block>>>(x, y, out, n, m);
}